// round 2
// baseline (speedup 1.0000x reference)
#include <cuda_runtime.h>
#include <cuda_bf16.h>

// FM_12060268167845: factorization machine forward.
// Inputs (metadata order):
//   d_in[0] idx    int32  [B,K]
//   d_in[1] x_vals f32    [B,K]
//   d_in[2] b_vals f32    [B,K]
//   d_in[3] w      f32    [INPUT_DIM,1]
//   d_in[4] V      f32    [INPUT_DIM,F]
//   d_in[5] bias   f32    [1]
// Output: f32 [B] = sigmoid(bias + Xw + 0.5/sum(x) * sum_f((XV)^2 - X2V2))

#define FM_B 8192
#define FM_K 200
#define FM_F 128

__global__ __launch_bounds__(FM_F, 8)
void fm_kernel(const int* __restrict__ idx,
               const float* __restrict__ x_vals,
               const float* __restrict__ b_vals,
               const float* __restrict__ w,
               const float* __restrict__ V,
               const float* __restrict__ bias,
               float* __restrict__ out)
{
    const int b = blockIdx.x;
    const int f = threadIdx.x;           // 0..127, factor index
    const int lane = f & 31;
    const int warp = f >> 5;

    __shared__ int   s_idx[FM_K];
    __shared__ float s_x[FM_K];
    __shared__ float s_red[3][4];

    // Stage indices + x into shared; fold in the linear term and sum(x).
    float xw = 0.0f;   // sum_k b_vals * w[idx]
    float sx = 0.0f;   // sum_k x_vals
    const int base = b * FM_K;
    for (int k = f; k < FM_K; k += FM_F) {
        int   id = idx[base + k];
        float xv = x_vals[base + k];
        s_idx[k] = id;
        s_x[k]   = xv;
        sx += xv;
        xw = fmaf(b_vals[base + k], __ldg(&w[id]), xw);
    }
    __syncthreads();

    // Main gather loop: thread f accumulates factor f across all K features.
    float a1 = 0.0f;   // XV[f]
    float a2 = 0.0f;   // X2V2[f]
    #pragma unroll 4
    for (int k = 0; k < FM_K; ++k) {
        float v  = __ldg(&V[(long)s_idx[k] * FM_F + f]);
        float xk = s_x[k];
        a1 = fmaf(xk, v, a1);
        a2 = fmaf(xk * xk, v * v, a2);
    }

    // Per-thread interaction contribution, then block reduction of
    // (pq, xw, sx) over the 128 threads.
    float pq = fmaf(a1, a1, -a2);

    #pragma unroll
    for (int o = 16; o > 0; o >>= 1) {
        pq += __shfl_down_sync(0xffffffffu, pq, o);
        xw += __shfl_down_sync(0xffffffffu, xw, o);
        sx += __shfl_down_sync(0xffffffffu, sx, o);
    }
    if (lane == 0) {
        s_red[0][warp] = pq;
        s_red[1][warp] = xw;
        s_red[2][warp] = sx;
    }
    __syncthreads();

    if (f == 0) {
        float PQ = s_red[0][0] + s_red[0][1] + s_red[0][2] + s_red[0][3];
        float XW = s_red[1][0] + s_red[1][1] + s_red[1][2] + s_red[1][3];
        float SX = s_red[2][0] + s_red[2][1] + s_red[2][2] + s_red[2][3];
        float p = 0.5f * (1.0f / SX) * PQ;
        float logit = bias[0] + XW + p;
        out[b] = 1.0f / (1.0f + __expf(-logit));
    }
}

extern "C" void kernel_launch(void* const* d_in, const int* in_sizes, int n_in,
                              void* d_out, int out_size)
{
    const int*   idx    = (const int*)d_in[0];
    const float* x_vals = (const float*)d_in[1];
    const float* b_vals = (const float*)d_in[2];
    const float* w      = (const float*)d_in[3];
    const float* V      = (const float*)d_in[4];
    const float* bias   = (const float*)d_in[5];
    float*       out    = (float*)d_out;
    (void)in_sizes; (void)n_in; (void)out_size;

    fm_kernel<<<FM_B, FM_F>>>(idx, x_vals, b_vals, w, V, bias, out);
}

// round 3
// speedup vs baseline: 1.0776x; 1.0776x over previous
#include <cuda_runtime.h>
#include <cuda_bf16.h>

// FM_12060268167845: factorization machine forward.
// Inputs (metadata order):
//   d_in[0] idx    int32  [B,K]
//   d_in[1] x_vals f32    [B,K]
//   d_in[2] b_vals f32    [B,K]
//   d_in[3] w      f32    [INPUT_DIM,1]
//   d_in[4] V      f32    [INPUT_DIM,F]   (F=128 -> 512B rows, 512B-aligned)
//   d_in[5] bias   f32    [1]
// Output: f32 [B] = sigmoid(bias + Xw + 0.5/sum(x) * sum_f((XV)^2 - X2V2))
//
// v2: one warp per batch row. Each lane owns 4 factors via float4 ->
// one k-iteration is a single warp-wide LDG.128 fetching the whole 512B
// V row as one contiguous burst. 4x fewer load instructions, 4x more
// bytes in flight per instruction, better DRAM row locality.

#define FM_B 8192
#define FM_K 200
#define FM_F 128
#define ROWS_PER_BLOCK 4
#define THREADS (ROWS_PER_BLOCK * 32)

__global__ __launch_bounds__(THREADS, 8)
void fm_kernel(const int* __restrict__ idx,
               const float* __restrict__ x_vals,
               const float* __restrict__ b_vals,
               const float* __restrict__ w,
               const float* __restrict__ V,
               const float* __restrict__ bias,
               float* __restrict__ out)
{
    const int warp = threadIdx.x >> 5;
    const int lane = threadIdx.x & 31;
    const int b    = blockIdx.x * ROWS_PER_BLOCK + warp;

    __shared__ int   s_idx[ROWS_PER_BLOCK][FM_K];
    __shared__ float s_x[ROWS_PER_BLOCK][FM_K];

    // Stage idx + x into per-warp shared; fold in linear term and sum(x).
    float xw = 0.0f;   // sum_k b_vals * w[idx]
    float sx = 0.0f;   // sum_k x_vals
    const int base = b * FM_K;
    for (int k = lane; k < FM_K; k += 32) {
        int   id = idx[base + k];
        float xv = x_vals[base + k];
        s_idx[warp][k] = id;
        s_x[warp][k]   = xv;
        sx += xv;
        xw = fmaf(b_vals[base + k], __ldg(&w[id]), xw);
    }
    __syncwarp();

    // Main gather: lane owns factors [4*lane, 4*lane+4). One LDG.128 per
    // lane per k -> warp fetches the full 512B row in one request.
    const float4* __restrict__ V4 = (const float4*)V;
    float4 a1 = make_float4(0.f, 0.f, 0.f, 0.f);
    float4 a2 = make_float4(0.f, 0.f, 0.f, 0.f);

    #pragma unroll 4
    for (int k = 0; k < FM_K; ++k) {
        float4 v  = __ldg(&V4[(long)s_idx[warp][k] * (FM_F / 4) + lane]);
        float  x  = s_x[warp][k];
        float  x2 = x * x;
        a1.x = fmaf(x, v.x, a1.x);
        a1.y = fmaf(x, v.y, a1.y);
        a1.z = fmaf(x, v.z, a1.z);
        a1.w = fmaf(x, v.w, a1.w);
        a2.x = fmaf(x2, v.x * v.x, a2.x);
        a2.y = fmaf(x2, v.y * v.y, a2.y);
        a2.z = fmaf(x2, v.z * v.z, a2.z);
        a2.w = fmaf(x2, v.w * v.w, a2.w);
    }

    // Per-lane interaction contribution over its 4 factors.
    float pq = (a1.x * a1.x - a2.x) + (a1.y * a1.y - a2.y)
             + (a1.z * a1.z - a2.z) + (a1.w * a1.w - a2.w);

    // Warp reduction of (pq, xw, sx).
    #pragma unroll
    for (int o = 16; o > 0; o >>= 1) {
        pq += __shfl_down_sync(0xffffffffu, pq, o);
        xw += __shfl_down_sync(0xffffffffu, xw, o);
        sx += __shfl_down_sync(0xffffffffu, sx, o);
    }

    if (lane == 0) {
        float p     = 0.5f * (1.0f / sx) * pq;
        float logit = bias[0] + xw + p;
        out[b] = 1.0f / (1.0f + __expf(-logit));
    }
}

extern "C" void kernel_launch(void* const* d_in, const int* in_sizes, int n_in,
                              void* d_out, int out_size)
{
    const int*   idx    = (const int*)d_in[0];
    const float* x_vals = (const float*)d_in[1];
    const float* b_vals = (const float*)d_in[2];
    const float* w      = (const float*)d_in[3];
    const float* V      = (const float*)d_in[4];
    const float* bias   = (const float*)d_in[5];
    float*       out    = (float*)d_out;
    (void)in_sizes; (void)n_in; (void)out_size;

    fm_kernel<<<FM_B / ROWS_PER_BLOCK, THREADS>>>(idx, x_vals, b_vals, w, V, bias, out);
}

// round 4
// speedup vs baseline: 1.3070x; 1.2129x over previous
#include <cuda_runtime.h>
#include <cuda_bf16.h>

// FM_12060268167845: factorization machine forward.
// Inputs (metadata order):
//   d_in[0] idx    int32  [B,K]
//   d_in[1] x_vals f32    [B,K]
//   d_in[2] b_vals f32    [B,K]
//   d_in[3] w      f32    [INPUT_DIM,1]
//   d_in[4] V      f32    [INPUT_DIM,F]   (F=128 -> 512B rows)
//   d_in[5] bias   f32    [1]
// Output: f32 [B] = sigmoid(bias + Xw + 0.5/sum(x) * sum_f((XV)^2 - X2V2))
//
// v3: one warp per batch row, lane owns 4 factors (float4 = warp-wide 512B
// row burst). Explicit U=8 load batching -> 8 LDG.128 in flight per warp
// (256 lines/SM at 8 CTAs/SM) to cover DRAM latency. X2V2 accumulated as
// a scalar (sum over f is all we need), staged {byte_off, x} pairs give a
// single LDS.64 per k in the address path.

#define FM_B 8192
#define FM_K 200
#define FM_F 128
#define ROWS_PER_BLOCK 4
#define THREADS (ROWS_PER_BLOCK * 32)
#define U 8                       // FM_K % U == 0

struct __align__(8) OffX { unsigned off; float x; };

__global__ __launch_bounds__(THREADS, 8)
void fm_kernel(const int* __restrict__ idx,
               const float* __restrict__ x_vals,
               const float* __restrict__ b_vals,
               const float* __restrict__ w,
               const float* __restrict__ V,
               const float* __restrict__ bias,
               float* __restrict__ out)
{
    const int warp = threadIdx.x >> 5;
    const int lane = threadIdx.x & 31;
    const int b    = blockIdx.x * ROWS_PER_BLOCK + warp;

    __shared__ OffX s_ox[ROWS_PER_BLOCK][FM_K];

    // Stage {byte offset, x} into shared; fold in linear term and sum(x).
    float xw = 0.0f;   // sum_k b_vals * w[idx]
    float sx = 0.0f;   // sum_k x_vals
    const int base = b * FM_K;
    for (int k = lane; k < FM_K; k += 32) {
        int   id = idx[base + k];
        float xv = x_vals[base + k];
        OffX ox;
        ox.off = (unsigned)id * (FM_F * 4u);   // id * 512 bytes, fits u32
        ox.x   = xv;
        s_ox[warp][k] = ox;
        sx += xv;
        xw = fmaf(b_vals[base + k], __ldg(&w[id]), xw);
    }
    __syncwarp();

    const char* __restrict__ Vb = (const char*)V;
    const unsigned lane_off = (unsigned)lane << 4;   // lane * 16 bytes

    float4 a1  = make_float4(0.f, 0.f, 0.f, 0.f);    // XV[4 factors]
    float  a2s = 0.0f;                               // sum_f X2V2 (lane slice)

    for (int k0 = 0; k0 < FM_K; k0 += U) {
        float4 v[U];
        float  xr[U];
        // Front-batch U independent LDG.128s.
        #pragma unroll
        for (int u = 0; u < U; ++u) {
            OffX ox = s_ox[warp][k0 + u];
            xr[u] = ox.x;
            v[u]  = __ldg((const float4*)(Vb + ox.off + lane_off));
        }
        #pragma unroll
        for (int u = 0; u < U; ++u) {
            float x  = xr[u];
            float x2 = x * x;
            a1.x = fmaf(x, v[u].x, a1.x);
            a1.y = fmaf(x, v[u].y, a1.y);
            a1.z = fmaf(x, v[u].z, a1.z);
            a1.w = fmaf(x, v[u].w, a1.w);
            float n2 = fmaf(v[u].x, v[u].x,
                       fmaf(v[u].y, v[u].y,
                       fmaf(v[u].z, v[u].z, v[u].w * v[u].w)));
            a2s = fmaf(x2, n2, a2s);
        }
    }

    // Per-lane interaction contribution over its 4 factors.
    float pq = fmaf(a1.x, a1.x,
               fmaf(a1.y, a1.y,
               fmaf(a1.z, a1.z, a1.w * a1.w))) - a2s;

    // Warp reduction of (pq, xw, sx).
    #pragma unroll
    for (int o = 16; o > 0; o >>= 1) {
        pq += __shfl_down_sync(0xffffffffu, pq, o);
        xw += __shfl_down_sync(0xffffffffu, xw, o);
        sx += __shfl_down_sync(0xffffffffu, sx, o);
    }

    if (lane == 0) {
        float p     = 0.5f * (1.0f / sx) * pq;
        float logit = bias[0] + xw + p;
        out[b] = 1.0f / (1.0f + __expf(-logit));
    }
}

extern "C" void kernel_launch(void* const* d_in, const int* in_sizes, int n_in,
                              void* d_out, int out_size)
{
    const int*   idx    = (const int*)d_in[0];
    const float* x_vals = (const float*)d_in[1];
    const float* b_vals = (const float*)d_in[2];
    const float* w      = (const float*)d_in[3];
    const float* V      = (const float*)d_in[4];
    const float* bias   = (const float*)d_in[5];
    float*       out    = (float*)d_out;
    (void)in_sizes; (void)n_in; (void)out_size;

    fm_kernel<<<FM_B / ROWS_PER_BLOCK, THREADS>>>(idx, x_vals, b_vals, w, V, bias, out);
}